// round 7
// baseline (speedup 1.0000x reference)
#include <cuda_runtime.h>

#define Bsz 4
#define Nn 300
#define TOP 36
#define Cc 2048
#define Dd 2048
#define NROI (Bsz*TOP)

// ---------------- scratch (device globals, no allocation) ----------------
__device__ int   g_valid[NROI];
__device__ int   g_level[NROI];
__device__ int   g_dest[NROI];
__device__ int   g_ny[NROI], g_nx[NROI];
__device__ int   g_yi[NROI][28], g_xi[NROI][28];
__device__ float g_yw[NROI][28], g_xw[NROI][28];
__device__ float g_pooled[NROI][Cc];
__device__ int   g_order[NROI];

#define KSPLIT 16
__device__ float g_part[KSPLIT][NROI][Dd];

__device__ __forceinline__ int level_size(int l) {
    return (l == 0) ? 100 : (l == 1) ? 50 : (l == 2) ? 25 : 13;
}

// Streaming separable axis table: 14 monotone samples -> merged (idx, weight)
// list (<=28 entries). Exactly replicates reference bilinear accumulation.
__device__ int build_axis(float start, float rlen, int Hs, int* gidx, float* gwt) {
    int   li[28];
    float lw[28];
    int n = 0;
    float step7  = rlen / 7.0f;
    float step14 = rlen / 14.0f;
    for (int i = 0; i < 14; i++) {
        float yy = start + (float)(i >> 1) * step7 + ((float)(i & 1) + 0.5f) * step14;
        if (yy < -1.0f || yy > (float)Hs) continue;
        float yc = fminf(fmaxf(yy, 0.0f), (float)Hs - 1.0f);
        int i0 = (int)floorf(yc);
        int i1 = min(i0 + 1, Hs - 1);
        float w = yc - (float)i0;
        float w0 = 1.0f - w;
        if (n > 0 && li[n-1] == i0)      lw[n-1] += w0;
        else if (n > 1 && li[n-2] == i0) lw[n-2] += w0;
        else { li[n] = i0; lw[n] = w0; n++; }
        if (n > 0 && li[n-1] == i1)      lw[n-1] += w;
        else if (n > 1 && li[n-2] == i1) lw[n-2] += w;
        else { li[n] = i1; lw[n] = w; n++; }
    }
    for (int t = 0; t < n; t++) { gidx[t] = li[t]; gwt[t] = lw[t]; }
    return n;
}

// ---------------- kernel 1: filter + sort + warp NMS + tables + dest ----------------
__global__ void select_kernel(const float* __restrict__ boxes,
                              const float* __restrict__ scores) {
    int b = blockIdx.x;
    int tid = threadIdx.x;
    __shared__ float ss[Nn];
    __shared__ float sx1[Nn], sy1[Nn], sx2[Nn], sy2[Nn];
    __shared__ int   s_selidx[TOP];
    __shared__ int   s_cnt;
    __shared__ int   s_M;
    __shared__ int   keys[TOP];

    const float* sc = scores + b * Nn;
    const float* bx = boxes + (size_t)b * Nn * 4;

    if (tid == 0) s_M = 0;
    for (int i = tid; i < Nn; i += blockDim.x) ss[i] = sc[i];
    __syncthreads();

    {
        int local = 0;
        for (int i = tid; i < Nn; i += blockDim.x) local += (ss[i] > 0.3f);
        #pragma unroll
        for (int o = 16; o; o >>= 1) local += __shfl_down_sync(0xffffffffu, local, o);
        if ((tid & 31) == 0 && local) atomicAdd(&s_M, local);
    }

    for (int i = tid; i < Nn; i += blockDim.x) {
        float si = ss[i];
        if (si > 0.3f) {
            int rank = 0;
            for (int j = 0; j < Nn; j++) {
                float sj = ss[j];
                rank += (sj > 0.3f) && ((sj > si) || (sj == si && j < i));
            }
            sx1[rank] = bx[i * 4 + 0];
            sy1[rank] = bx[i * 4 + 1];
            sx2[rank] = bx[i * 4 + 2];
            sy2[rank] = bx[i * 4 + 3];
        }
    }
    __syncthreads();

    int M = s_M;

    if (tid < 32) {
        int lane = tid;
        unsigned kmask = 0;
        #pragma unroll
        for (int s2 = 0; s2 < 10; s2++)
            if (lane + 32 * s2 < M) kmask |= (1u << s2);
        int cnt = 0;
        for (int i = 0; i < M; i++) {
            unsigned om = __shfl_sync(0xffffffffu, kmask, i & 31);
            if (!((om >> (i >> 5)) & 1u)) continue;
            if (lane == 0) s_selidx[cnt] = i;
            cnt++;
            if (cnt >= TOP) break;
            float x1 = sx1[i], y1 = sy1[i], x2 = sx2[i], y2 = sy2[i];
            float ai = (x2 - x1) * (y2 - y1);
            #pragma unroll
            for (int s2 = 0; s2 < 10; s2++) {
                int j = lane + 32 * s2;
                if (((kmask >> s2) & 1u) && j > i && j < M) {
                    float jx1 = sx1[j], jy1 = sy1[j], jx2 = sx2[j], jy2 = sy2[j];
                    float xx1 = fmaxf(x1, jx1);
                    float yy1 = fmaxf(y1, jy1);
                    float xx2 = fminf(x2, jx2);
                    float yy2 = fminf(y2, jy2);
                    float inter = fmaxf(xx2 - xx1, 0.0f) * fmaxf(yy2 - yy1, 0.0f);
                    float aj = (jx2 - jx1) * (jy2 - jy1);
                    float iou = inter / (ai + aj - inter);
                    if (iou > 0.7f) kmask &= ~(1u << s2);
                }
            }
        }
        if (lane == 0) s_cnt = cnt;
    }
    __syncthreads();

    if (tid < TOP) {
        int r = tid;
        int roi = b * TOP + r;
        int valid = 0, lvl = 0;
        if (r < s_cnt) {
            valid = 1;
            int i = s_selidx[r];
            float bx0 = sx1[i], bx1 = sy1[i], bx2 = sx2[i], bx3 = sy2[i];
            float dx = bx2 - bx0, dy = bx3 - bx1;
            float diag = sqrtf(dx * dx + dy * dy);
            float lf = floorf(4.0f + log2f(diag / 224.0f * 4.0f));
            lf = fminf(fmaxf(lf, 2.0f), 5.0f);
            lvl = (int)lf - 2;
            int Hs = level_size(lvl);
            float rw = fmaxf(bx2 - bx0, 1.0f);
            float rh = fmaxf(bx3 - bx1, 1.0f);
            g_ny[roi] = build_axis(bx1, rh, Hs, g_yi[roi], g_yw[roi]);
            g_nx[roi] = build_axis(bx0, rw, Hs, g_xi[roi], g_xw[roi]);
        } else {
            g_ny[roi] = 0;
            g_nx[roi] = 0;
        }
        g_valid[roi] = valid;
        g_level[roi] = lvl;
        keys[r] = valid ? (lvl * TOP + r) : (4 * TOP + r);
    }
    __syncthreads();
    if (tid < TOP) {
        int k = keys[tid];
        int d = 0;
        for (int q = 0; q < TOP; q++) d += (keys[q] < k);
        g_dest[b * TOP + tid] = d;
    }
}

// ---------------- kernel 1b: LPT ordering (slow level-0 rois first) ----------------
__global__ void schedule_kernel() {
    __shared__ int keys[NROI];
    int t = threadIdx.x;
    if (t < NROI) {
        int lvl = g_level[t];
        int img = t / TOP;
        keys[t] = g_valid[t] ? (lvl * 8 + img) : 1024;
    }
    __syncthreads();
    if (t < NROI) {
        int k = keys[t];
        int rank = 0;
        for (int j = 0; j < NROI; j++)
            rank += (keys[j] < k) || (keys[j] == k && j < t);
        g_order[rank] = t;
    }
}

// ---------------- kernel 2: ROI pooling ----------------
// grid: (NROI, 32), block: 256 threads. 64 channels per block.
// Warp handles 8 channels as 2 quads; per iter 4 planes x 4 taps = 16 LDGs in flight.
// Taps packed (offset, weight) in one int2 -> single LDS.64 per tap.
__global__ void pool_kernel(const float* __restrict__ f0, const float* __restrict__ f1,
                            const float* __restrict__ f2, const float* __restrict__ f3) {
    int roi  = g_order[blockIdx.x];
    int cblk = blockIdx.y;
    int tid  = threadIdx.x;

    if (!g_valid[roi]) {
        if (tid < 64) g_pooled[roi][cblk * 64 + tid] = 0.0f;
        return;
    }

    __shared__ int2 stap[784];

    int lvl = g_level[roi];
    int Hs  = level_size(lvl);
    int HW  = Hs * Hs;
    const float* fm = (lvl == 0) ? f0 : (lvl == 1) ? f1 : (lvl == 2) ? f2 : f3;

    int ny = g_ny[roi], nx = g_nx[roi];
    int n = ny * nx;
    for (int k = tid; k < n; k += 256) {
        int a = k / nx;
        int q = k - a * nx;
        stap[k] = make_int2(g_yi[roi][a] * Hs + g_xi[roi][q],
                            __float_as_int(g_yw[roi][a] * g_xw[roi][q]));
    }
    __syncthreads();

    int bimg = roi / TOP;
    int warp = tid >> 5, lane = tid & 31;
    #pragma unroll
    for (int q = 0; q < 2; q++) {
        int c = cblk * 64 + (warp << 3) + (q << 2);
        const float* b0 = fm + ((size_t)(bimg * Cc + c)) * (size_t)HW;
        const float* b1 = b0 + HW;
        const float* b2 = b1 + HW;
        const float* b3 = b2 + HW;
        float a0 = 0.f, a1 = 0.f, a2 = 0.f, a3 = 0.f;
        int k = lane;
        for (; k + 96 < n; k += 128) {
            int2 t0 = stap[k], t1 = stap[k + 32], t2 = stap[k + 64], t3 = stap[k + 96];
            float w0 = __int_as_float(t0.y), w1 = __int_as_float(t1.y);
            float w2 = __int_as_float(t2.y), w3 = __int_as_float(t3.y);
            float p00 = b0[t0.x], p01 = b0[t1.x], p02 = b0[t2.x], p03 = b0[t3.x];
            float p10 = b1[t0.x], p11 = b1[t1.x], p12 = b1[t2.x], p13 = b1[t3.x];
            float p20 = b2[t0.x], p21 = b2[t1.x], p22 = b2[t2.x], p23 = b2[t3.x];
            float p30 = b3[t0.x], p31 = b3[t1.x], p32 = b3[t2.x], p33 = b3[t3.x];
            a0 += p00 * w0 + p01 * w1 + p02 * w2 + p03 * w3;
            a1 += p10 * w0 + p11 * w1 + p12 * w2 + p13 * w3;
            a2 += p20 * w0 + p21 * w1 + p22 * w2 + p23 * w3;
            a3 += p30 * w0 + p31 * w1 + p32 * w2 + p33 * w3;
        }
        for (; k < n; k += 32) {
            int2 t = stap[k];
            float w = __int_as_float(t.y);
            a0 += b0[t.x] * w;  a1 += b1[t.x] * w;
            a2 += b2[t.x] * w;  a3 += b3[t.x] * w;
        }
        #pragma unroll
        for (int o = 16; o; o >>= 1) {
            a0 += __shfl_down_sync(0xffffffffu, a0, o);
            a1 += __shfl_down_sync(0xffffffffu, a1, o);
            a2 += __shfl_down_sync(0xffffffffu, a2, o);
            a3 += __shfl_down_sync(0xffffffffu, a3, o);
        }
        if (lane == 0) {
            g_pooled[roi][c]     = a0 * (1.0f / 196.0f);
            g_pooled[roi][c + 1] = a1 * (1.0f / 196.0f);
            g_pooled[roi][c + 2] = a2 * (1.0f / 196.0f);
            g_pooled[roi][c + 3] = a3 * (1.0f / 196.0f);
        }
    }
}

// ---------------- kernel 3: split-K=16 GEMM, double-buffered, 6x8 tile, f32x2 ----------------
#define BM 48
#define BN 128
#define BK 16
#define KSEG (Cc / KSPLIT)   // 128
#define NIT  (KSEG / BK)     // 8

__global__ void __launch_bounds__(128) gemm_kernel(const float* __restrict__ Wm) {
    __shared__ float As[2][BK][BM];
    __shared__ float Bs[2][BK][BN + 4];

    int m0 = blockIdx.y * BM;
    int n0 = blockIdx.x * BN;
    int ks = blockIdx.z;
    int kbase = ks * KSEG;

    int tid = threadIdx.x;          // 128
    int ti = tid & 7;               // 8 m-groups of 6
    int tj = tid >> 3;              // 16 n-groups of 8

    unsigned long long acc2[6][4] = {};

    float  a_r[6];
    float4 b_r[4];

    const float* wrow = Wm + (size_t)(n0 + tid) * Cc + kbase;

    // prologue: tile 0
    #pragma unroll
    for (int q = 0; q < 6; q++) {
        int e = tid + q * 128;
        a_r[q] = g_pooled[m0 + (e >> 4)][kbase + (e & 15)];
    }
    #pragma unroll
    for (int j = 0; j < 4; j++)
        b_r[j] = reinterpret_cast<const float4*>(wrow)[j];
    #pragma unroll
    for (int q = 0; q < 6; q++) {
        int e = tid + q * 128;
        As[0][e & 15][e >> 4] = a_r[q];
    }
    #pragma unroll
    for (int j = 0; j < 4; j++) {
        Bs[0][4 * j + 0][tid] = b_r[j].x;
        Bs[0][4 * j + 1][tid] = b_r[j].y;
        Bs[0][4 * j + 2][tid] = b_r[j].z;
        Bs[0][4 * j + 3][tid] = b_r[j].w;
    }
    __syncthreads();

    int buf = 0;
    for (int it = 0; it < NIT; it++) {
        if (it + 1 < NIT) {
            int k0 = (it + 1) * BK;
            #pragma unroll
            for (int q = 0; q < 6; q++) {
                int e = tid + q * 128;
                a_r[q] = g_pooled[m0 + (e >> 4)][kbase + k0 + (e & 15)];
            }
            #pragma unroll
            for (int j = 0; j < 4; j++)
                b_r[j] = reinterpret_cast<const float4*>(wrow + k0)[j];
        }

        #pragma unroll
        for (int kk = 0; kk < BK; kk++) {
            unsigned long long bb[4];
            const float* brow = &Bs[buf][kk][tj * 8];
            #pragma unroll
            for (int v = 0; v < 2; v++) {
                float4 bv = *reinterpret_cast<const float4*>(brow + 4 * v);
                asm("mov.b64 %0, {%1, %2};" : "=l"(bb[2*v])   : "f"(bv.x), "f"(bv.y));
                asm("mov.b64 %0, {%1, %2};" : "=l"(bb[2*v+1]) : "f"(bv.z), "f"(bv.w));
            }
            const float* arow = &As[buf][kk][ti * 6];
            #pragma unroll
            for (int u = 0; u < 6; u++) {
                float av = arow[u];
                unsigned long long ad;
                asm("mov.b64 %0, {%1, %1};" : "=l"(ad) : "f"(av));
                #pragma unroll
                for (int v = 0; v < 4; v++)
                    asm("fma.rn.f32x2 %0, %1, %2, %0;" : "+l"(acc2[u][v]) : "l"(ad), "l"(bb[v]));
            }
        }

        if (it + 1 < NIT) {
            int nb = buf ^ 1;
            #pragma unroll
            for (int q = 0; q < 6; q++) {
                int e = tid + q * 128;
                As[nb][e & 15][e >> 4] = a_r[q];
            }
            #pragma unroll
            for (int j = 0; j < 4; j++) {
                Bs[nb][4 * j + 0][tid] = b_r[j].x;
                Bs[nb][4 * j + 1][tid] = b_r[j].y;
                Bs[nb][4 * j + 2][tid] = b_r[j].z;
                Bs[nb][4 * j + 3][tid] = b_r[j].w;
            }
        }
        __syncthreads();
        buf ^= 1;
    }

    #pragma unroll
    for (int u = 0; u < 6; u++) {
        int m = m0 + ti * 6 + u;
        float* prow = &g_part[ks][m][n0 + tj * 8];
        #pragma unroll
        for (int v = 0; v < 4; v++)
            *reinterpret_cast<unsigned long long*>(&prow[2 * v]) = acc2[u][v];
    }
}

// ---------------- kernel 4: combine partials + bias + mask + permute ----------------
__global__ void combine_kernel(const float* __restrict__ bias,
                               float* __restrict__ out) {
    int m = blockIdx.x;                         // 144
    int n = blockIdx.y * 256 + threadIdx.x;     // 2048
    int bimg = m / TOP;
    float v = 0.0f;
    if (g_valid[m]) {
        v = bias[n];
        #pragma unroll
        for (int s = 0; s < KSPLIT; s++)
            v += g_part[s][m][n];
    }
    out[((size_t)(bimg * TOP + g_dest[m])) * Dd + n] = v;
}

// ---------------- launch ----------------
extern "C" void kernel_launch(void* const* d_in, const int* in_sizes, int n_in,
                              void* d_out, int out_size) {
    const float* boxes  = (const float*)d_in[0];
    const float* scores = (const float*)d_in[1];
    const float* f0     = (const float*)d_in[2];
    const float* f1     = (const float*)d_in[3];
    const float* f2     = (const float*)d_in[4];
    const float* f3     = (const float*)d_in[5];
    const float* Wm     = (const float*)d_in[6];
    const float* bias   = (const float*)d_in[7];
    float* out = (float*)d_out;

    select_kernel<<<Bsz, 128>>>(boxes, scores);
    schedule_kernel<<<1, 160>>>();
    pool_kernel<<<dim3(NROI, 32), 256>>>(f0, f1, f2, f3);
    gemm_kernel<<<dim3(Dd / BN, NROI / BM, KSPLIT), 128>>>(Wm);
    combine_kernel<<<dim3(NROI, Dd / 256), 256>>>(bias, out);
}